// round 2
// baseline (speedup 1.0000x reference)
#include <cuda_runtime.h>
#include <math.h>

// support [25,2560] f32, query [4096,2560] f32 -> out [4096,5] f32
#define D      2560
#define NS     25
#define NQ     4096
#define NWAY   5
#define KSHOT  5
#define EPSV   1e-6f

#define DHALF  1280           // D split in 2 across blockIdx.y
#define KT     256            // K-tile staged in smem
#define ROWS_PER_CTA 64       // 8 warps x 8 rows
#define THREADS 256

typedef unsigned long long u64;

__device__ float g_snorm[NS];
// partial dots per d-half: [half][row][s(0..24), qn at 31]
__device__ float g_part[2][NQ][32];

// packed f32x2 FMA (Blackwell): d = a*b + c lanewise on 2 packed floats
__device__ __forceinline__ u64 ffma2(u64 a, u64 b, u64 c) {
    u64 d;
    asm("fma.rn.f32x2 %0, %1, %2, %3;" : "=l"(d) : "l"(a), "l"(b), "l"(c));
    return d;
}
__device__ __forceinline__ float f2_sum(u64 v) {
    float lo = __uint_as_float((unsigned)(v & 0xffffffffull));
    float hi = __uint_as_float((unsigned)(v >> 32));
    return lo + hi;
}

// ---------------------------------------------------------------------------
__global__ void prep_snorm_kernel(const float* __restrict__ support) {
    const int s = blockIdx.x;
    const float* row = support + (size_t)s * D;
    float acc = 0.f;
    for (int idx = threadIdx.x; idx < D / 4; idx += blockDim.x) {
        float4 v = *reinterpret_cast<const float4*>(row + idx * 4);
        float x = v.x + EPSV, y = v.y + EPSV, z = v.z + EPSV, w = v.w + EPSV;
        acc = fmaf(x, x, acc); acc = fmaf(y, y, acc);
        acc = fmaf(z, z, acc); acc = fmaf(w, w, acc);
    }
    #pragma unroll
    for (int off = 16; off > 0; off >>= 1)
        acc += __shfl_xor_sync(0xffffffffu, acc, off);
    __shared__ float ws[8];
    const int warp = threadIdx.x >> 5, lane = threadIdx.x & 31;
    if (lane == 0) ws[warp] = acc;
    __syncthreads();
    if (threadIdx.x == 0) {
        float t = 0.f;
        #pragma unroll
        for (int i = 0; i < 8; ++i) t += ws[i];
        g_snorm[s] = t;
    }
}

// ---------------------------------------------------------------------------
// Stage 1: partial dot(q, s+eps) and partial ||q||^2 over one D-half.
// CTA = 64 query rows, 8 warps. Warp covers 8 rows.
// Lane = (rg in 0..3, c in 0..7): 2 rows (rg*2, rg*2+1), 16B column slice c.
// Support smem reads are 4-way multicast across rg -> 0.5 smem bytes/MAC.
// Inner math is packed f32x2 FMA: 4 MACs per instruction per lane.
// ---------------------------------------------------------------------------
__global__ __launch_bounds__(THREADS, 1)
void pairdist_stage1(const float* __restrict__ support,
                     const float* __restrict__ query) {
    __shared__ float sS[NS][KT];

    const int tid  = threadIdx.x;
    const int warp = tid >> 5;
    const int ln   = tid & 31;
    const int rg   = ln >> 3;      // row group 0..3
    const int c    = ln & 7;       // column group 0..7
    const int dh   = blockIdx.y;   // d-half
    const int row0 = blockIdx.x * ROWS_PER_CTA + warp * 8 + rg * 2;
    const int dstart = dh * DHALF;

    u64 acc0[NS], acc1[NS];
    #pragma unroll
    for (int s = 0; s < NS; ++s) { acc0[s] = 0ull; acc1[s] = 0ull; }
    u64 qn0 = 0ull, qn1 = 0ull;

    const float* qr0 = query + (size_t)row0 * D + dstart;
    const float* qr1 = qr0 + D;

    for (int kt = 0; kt < DHALF; kt += KT) {
        __syncthreads();
        // stage support tile (+eps), coalesced float4
        for (int i = tid; i < NS * (KT / 4); i += THREADS) {
            const int s  = i / (KT / 4);
            const int c4 = (i - s * (KT / 4)) * 4;
            float4 v = *reinterpret_cast<const float4*>(
                support + (size_t)s * D + dstart + kt + c4);
            v.x += EPSV; v.y += EPSV; v.z += EPSV; v.w += EPSV;
            *reinterpret_cast<float4*>(&sS[s][c4]) = v;
        }
        __syncthreads();

        #pragma unroll
        for (int it = 0; it < KT / 32; ++it) {
            const int scol = it * 32 + c * 4;
            const ulonglong2 qa = *reinterpret_cast<const ulonglong2*>(qr0 + kt + scol);
            const ulonglong2 qb = *reinterpret_cast<const ulonglong2*>(qr1 + kt + scol);
            qn0 = ffma2(qa.x, qa.x, qn0); qn0 = ffma2(qa.y, qa.y, qn0);
            qn1 = ffma2(qb.x, qb.x, qn1); qn1 = ffma2(qb.y, qb.y, qn1);
            #pragma unroll
            for (int s = 0; s < NS; ++s) {
                const ulonglong2 sv = *reinterpret_cast<const ulonglong2*>(&sS[s][scol]);
                acc0[s] = ffma2(qa.x, sv.x, acc0[s]);
                acc0[s] = ffma2(qa.y, sv.y, acc0[s]);
                acc1[s] = ffma2(qb.x, sv.x, acc1[s]);
                acc1[s] = ffma2(qb.y, sv.y, acc1[s]);
            }
        }
    }

    // reduce across the 8 c-lanes within each rg group (xor 1,2,4 stay in-group)
    float d0[NS], d1[NS];
    #pragma unroll
    for (int s = 0; s < NS; ++s) { d0[s] = f2_sum(acc0[s]); d1[s] = f2_sum(acc1[s]); }
    float q0 = f2_sum(qn0), q1 = f2_sum(qn1);
    #pragma unroll
    for (int off = 4; off > 0; off >>= 1) {
        #pragma unroll
        for (int s = 0; s < NS; ++s) {
            d0[s] += __shfl_xor_sync(0xffffffffu, d0[s], off);
            d1[s] += __shfl_xor_sync(0xffffffffu, d1[s], off);
        }
        q0 += __shfl_xor_sync(0xffffffffu, q0, off);
        q1 += __shfl_xor_sync(0xffffffffu, q1, off);
    }

    if (c == 0) {
        #pragma unroll
        for (int s = 0; s < NS; ++s) {
            g_part[dh][row0][s]     = d0[s];
            g_part[dh][row0 + 1][s] = d1[s];
        }
        g_part[dh][row0][31]     = q0;
        g_part[dh][row0 + 1][31] = q1;
    }
}

// ---------------------------------------------------------------------------
// Stage 2: combine halves, dist = sqrt(qn + sn - 2 dot), score = -sum_k dist
// ---------------------------------------------------------------------------
__global__ void pairdist_stage2(float* __restrict__ out) {
    const int row = blockIdx.x * blockDim.x + threadIdx.x;
    if (row >= NQ) return;
    const float qn = g_part[0][row][31] + g_part[1][row][31];
    #pragma unroll
    for (int w = 0; w < NWAY; ++w) {
        float sum = 0.f;
        #pragma unroll
        for (int k = 0; k < KSHOT; ++k) {
            const int s = w * KSHOT + k;
            const float dot = g_part[0][row][s] + g_part[1][row][s];
            const float d2 = qn + g_snorm[s] - 2.f * dot;
            sum += sqrtf(fmaxf(d2, 0.f));
        }
        out[(size_t)row * NWAY + w] = -sum;
    }
}

// ---------------------------------------------------------------------------
extern "C" void kernel_launch(void* const* d_in, const int* in_sizes, int n_in,
                              void* d_out, int out_size) {
    const float* support = (const float*)d_in[0];
    const float* query   = (const float*)d_in[1];
    if (n_in >= 2 && in_sizes[0] > in_sizes[1]) {
        const float* t = support; support = query; query = t;
    }
    float* out = (float*)d_out;

    prep_snorm_kernel<<<NS, 256>>>(support);
    pairdist_stage1<<<dim3(NQ / ROWS_PER_CTA, 2), THREADS>>>(support, query);
    pairdist_stage2<<<NQ / 256, 256>>>(out);
}